// round 1
// baseline (speedup 1.0000x reference)
#include <cuda_runtime.h>
#include <cstdint>
#include <cstddef>

#define B_  2
#define S_  2048
#define D_  1024
#define H_  16
#define HD_ 64

#define NEG_INF (__int_as_float(0xff800000))

// 16 MB each — static device scratch (allocation-free rule)
__device__ float g_q[(size_t)B_ * H_ * S_ * HD_];
__device__ float g_k[(size_t)B_ * H_ * S_ * HD_];

// ---------------------------------------------------------------------------
// Kernel 1: qk = encoded @ W^T + bias ; scatter into g_q / g_k as [b][h][s][hd]
// ---------------------------------------------------------------------------
#define BM 128
#define BN 128
#define BK 8

__global__ __launch_bounds__(256) void proj_kernel(
    const float* __restrict__ A,     // [4096, 1024]
    const float* __restrict__ W,     // [2048, 1024]
    const float* __restrict__ bias)  // [2048]
{
    __shared__ float As[BK][BM + 4];
    __shared__ float Bs[BK][BN + 4];

    const int tid = threadIdx.x;
    const int m0  = blockIdx.y * BM;
    const int n0  = blockIdx.x * BN;
    const int tx  = tid & 15;
    const int ty  = tid >> 4;
    const int lrow = tid >> 1;          // 0..127
    const int lk4  = (tid & 1) << 2;    // 0 or 4

    const float* Ag = A + (size_t)(m0 + lrow) * D_ + lk4;
    const float* Wg = W + (size_t)(n0 + lrow) * D_ + lk4;

    float acc[8][8];
    #pragma unroll
    for (int i = 0; i < 8; i++)
        #pragma unroll
        for (int j = 0; j < 8; j++) acc[i][j] = 0.f;

    for (int k0 = 0; k0 < D_; k0 += BK) {
        float4 av = *(const float4*)(Ag + k0);
        float4 wv = *(const float4*)(Wg + k0);
        __syncthreads();
        As[lk4 + 0][lrow] = av.x; As[lk4 + 1][lrow] = av.y;
        As[lk4 + 2][lrow] = av.z; As[lk4 + 3][lrow] = av.w;
        Bs[lk4 + 0][lrow] = wv.x; Bs[lk4 + 1][lrow] = wv.y;
        Bs[lk4 + 2][lrow] = wv.z; Bs[lk4 + 3][lrow] = wv.w;
        __syncthreads();

        #pragma unroll
        for (int kk = 0; kk < BK; kk++) {
            float4 a0 = *(const float4*)&As[kk][ty * 8];
            float4 a1 = *(const float4*)&As[kk][ty * 8 + 4];
            float4 b0 = *(const float4*)&Bs[kk][tx * 8];
            float4 b1 = *(const float4*)&Bs[kk][tx * 8 + 4];
            float a[8] = {a0.x, a0.y, a0.z, a0.w, a1.x, a1.y, a1.z, a1.w};
            float b[8] = {b0.x, b0.y, b0.z, b0.w, b1.x, b1.y, b1.z, b1.w};
            #pragma unroll
            for (int i = 0; i < 8; i++)
                #pragma unroll
                for (int j = 0; j < 8; j++)
                    acc[i][j] = fmaf(a[i], b[j], acc[i][j]);
        }
    }

    // Epilogue: add bias, scatter to q/k scratch with [b][h][s][hd] layout.
    const int e0 = n0 + tx * 8;            // 8 consecutive e, same head block
    float bv[8];
    #pragma unroll
    for (int j = 0; j < 8; j++) bv[j] = bias[e0 + j];

    const bool is_q = (e0 < D_);
    const int  eh   = is_q ? e0 : (e0 - D_);
    const int  hh   = eh >> 6;
    const int  hd0  = eh & 63;
    float* dst = is_q ? g_q : g_k;

    #pragma unroll
    for (int i = 0; i < 8; i++) {
        const int m  = m0 + ty * 8 + i;
        const int bb = m >> 11;            // m / 2048
        const int s  = m & (S_ - 1);
        float* row = dst + (((size_t)bb * H_ + hh) * S_ + s) * HD_ + hd0;
        #pragma unroll
        for (int j = 0; j < 8; j++)
            row[j] = acc[i][j] + bv[j];
    }
}

// ---------------------------------------------------------------------------
// Kernel 2: causal scores + softmax. Block = 16 query rows for one (b,h).
// Warp w owns s-chunks j == w (mod 16); each lane accumulates 16 rows x 4
// chunk-slots of scores in registers. Row stats via shfl + smem reduce.
// ---------------------------------------------------------------------------
#define TQ 16

__global__ __launch_bounds__(512, 1) void attn_kernel(float* __restrict__ out)
{
    __shared__ float qs[TQ][68];        // stride 68: conflict-free float4
    __shared__ float red[16][17];
    __shared__ float rowmax_s[TQ];
    __shared__ float rowinv_s[TQ];

    const int tid = threadIdx.x;
    const int w   = tid >> 5;
    const int l   = tid & 31;
    const int t0  = blockIdx.x * TQ;
    const size_t bh = (size_t)blockIdx.z * H_ + blockIdx.y;

    const float* qg = g_q + (bh * S_ + t0) * HD_;
    const float* kg = g_k + bh * S_ * HD_;

    // Load Q tile (scale = 1/sqrt(64) folded into q)
    if (tid < 256) {
        const int r  = tid >> 4;
        const int c4 = (tid & 15) << 2;
        float4 v = *(const float4*)(qg + r * HD_ + c4);
        const float scale = 0.125f;
        v.x *= scale; v.y *= scale; v.z *= scale; v.w *= scale;
        *(float4*)&qs[r][c4] = v;
    }
    __syncthreads();

    const int nch = ((t0 + TQ - 1) >> 5) + 1;   // number of needed 32-wide s-chunks

    float sc[TQ][4];
    #pragma unroll
    for (int r = 0; r < TQ; r++)
        #pragma unroll
        for (int c = 0; c < 4; c++) sc[r][c] = 0.f;

    #pragma unroll
    for (int c = 0; c < 4; c++) {
        const int j = w + (c << 4);
        if (j < nch) {
            const int s = (j << 5) + l;
            const float4* kr = (const float4*)(kg + (size_t)s * HD_);
            #pragma unroll
            for (int hd4 = 0; hd4 < 16; hd4++) {
                const float4 kv = kr[hd4];
                #pragma unroll
                for (int r = 0; r < TQ; r++) {
                    const float4 qv = *(const float4*)&qs[r][hd4 << 2];
                    sc[r][c] = fmaf(kv.x, qv.x, sc[r][c]);
                    sc[r][c] = fmaf(kv.y, qv.y, sc[r][c]);
                    sc[r][c] = fmaf(kv.z, qv.z, sc[r][c]);
                    sc[r][c] = fmaf(kv.w, qv.w, sc[r][c]);
                }
            }
        }
    }

    // Causal mask + unvisited chunks -> -inf (exp -> exact 0, matching ref underflow)
    #pragma unroll
    for (int c = 0; c < 4; c++) {
        const int j = w + (c << 4);
        const int s = (j << 5) + l;
        #pragma unroll
        for (int r = 0; r < TQ; r++)
            if (j >= nch || s > t0 + r) sc[r][c] = NEG_INF;
    }

    // Row max: lane -> warp shfl -> cross-warp smem
    #pragma unroll
    for (int r = 0; r < TQ; r++) {
        float v = fmaxf(fmaxf(sc[r][0], sc[r][1]), fmaxf(sc[r][2], sc[r][3]));
        #pragma unroll
        for (int off = 16; off > 0; off >>= 1)
            v = fmaxf(v, __shfl_xor_sync(0xffffffffu, v, off));
        if (l == 0) red[w][r] = v;
    }
    __syncthreads();
    if (tid < TQ) {
        float v = red[0][tid];
        #pragma unroll
        for (int ww = 1; ww < 16; ww++) v = fmaxf(v, red[ww][tid]);
        rowmax_s[tid] = v;
    }
    __syncthreads();

    // exp + row sum
    #pragma unroll
    for (int r = 0; r < TQ; r++) {
        const float m = rowmax_s[r];
        float t = 0.f;
        #pragma unroll
        for (int c = 0; c < 4; c++) {
            const float e = __expf(sc[r][c] - m);
            sc[r][c] = e;
            t += e;
        }
        #pragma unroll
        for (int off = 16; off > 0; off >>= 1)
            t += __shfl_xor_sync(0xffffffffu, t, off);
        if (l == 0) red[w][r] = t;
    }
    __syncthreads();
    if (tid < TQ) {
        float v = 0.f;
        #pragma unroll
        for (int ww = 0; ww < 16; ww++) v += red[ww][tid];
        rowinv_s[tid] = 1.0f / v;
    }
    __syncthreads();

    float inv[TQ];
    #pragma unroll
    for (int r = 0; r < TQ; r++) inv[r] = rowinv_s[r];

    // Write: lane l covers s = 32*j + l -> 128B coalesced stores per (r, chunk)
    float* obase = out + (bh * S_ + t0) * (size_t)S_;
    #pragma unroll
    for (int c = 0; c < 4; c++) {
        const int j = w + (c << 4);
        const size_t so = (size_t)(j << 5) + l;
        #pragma unroll
        for (int r = 0; r < TQ; r++)
            obase[(size_t)r * S_ + so] = sc[r][c] * inv[r];
    }
}

// ---------------------------------------------------------------------------
extern "C" void kernel_launch(void* const* d_in, const int* in_sizes, int n_in,
                              void* d_out, int out_size)
{
    (void)in_sizes; (void)n_in; (void)out_size;
    const float* encoded = (const float*)d_in[0];  // [2, 2048, 1024]
    const float* W       = (const float*)d_in[1];  // [2048, 1024]
    const float* bias    = (const float*)d_in[2];  // [2048]
    float* out = (float*)d_out;                    // [2, 16, 2048, 2048]

    dim3 g1((2 * D_) / BN, (B_ * S_) / BM);        // (16, 32)
    proj_kernel<<<g1, 256>>>(encoded, W, bias);

    dim3 g2(S_ / TQ, H_, B_);                      // (128, 16, 2)
    attn_kernel<<<g2, 512>>>(out);
}